// round 14
// baseline (speedup 1.0000x reference)
#include <cuda_runtime.h>
#include <cuda_bf16.h>

// ============================================================================
// Problem constants
// ============================================================================
#define T_STEPS 128
#define BS      64
#define NP      64
#define H       256
#define OUTD    64
#define M_ROWS  (BS*NP)             // 4096
#define STATE_ELEMS (BS*NP*H)       // 1048576

// proj kernel smem (runs once)
#define BS_FLOATS   (256*68)
#define AS2_FLOATS  (2*16*132)
#define SMEM_BYTES  ((BS_FLOATS + AS2_FLOATS)*4)  // 86528

// Persistent kernel smem layout (floats)
#define XD    0                    // x/act dup  [256 k][68]
#define HD    17408                // h dup      [256 k][68]
#define BSOFF 34816                // B chunks   [2][16][264]
#define BSTRIDE (16*264)           // 4224
#define QV    43264                // q_s [32][65] / v_s [32][64]
#define PSMEM_FLOATS (QV + 2080)   // 45344
#define PSMEM_BYTES  (PSMEM_FLOATS*4)  // 181376

// ============================================================================
// Device scratch
// ============================================================================
__device__ float g_x[STATE_ELEMS];          // x0 init
__device__ float g_h2[2*STATE_ELEMS];       // parity-buffered h (cross-block)
__device__ float g_proj[T_STEPS*BS*H];
__device__ float g_lp[M_ROWS];
__device__ float g_sxstd[H];
__device__ float g_logdet;
__device__ unsigned g_keybits[512];
__device__ unsigned g_x0key[2];
__device__ unsigned g_barrier[BS];

// ============================================================================
// JAX Threefry-2x32 (partitionable mode)
// ============================================================================
__device__ __forceinline__ unsigned rotl32(unsigned v, int d) {
    return __funnelshift_l(v, v, d);
}

__device__ __forceinline__ void threefry2x32(unsigned k0, unsigned k1,
                                             unsigned x, unsigned y,
                                             unsigned &o0, unsigned &o1) {
    unsigned k2 = k0 ^ k1 ^ 0x1BD11BDAu;
    x += k0; y += k1;
#define TF_R(r) { x += y; y = rotl32(y, (r)); y ^= x; }
    TF_R(13) TF_R(15) TF_R(26) TF_R(6)
    x += k1; y += k2 + 1u;
    TF_R(17) TF_R(29) TF_R(16) TF_R(24)
    x += k2; y += k0 + 2u;
    TF_R(13) TF_R(15) TF_R(26) TF_R(6)
    x += k0; y += k1 + 3u;
    TF_R(17) TF_R(29) TF_R(16) TF_R(24)
    x += k1; y += k2 + 4u;
    TF_R(13) TF_R(15) TF_R(26) TF_R(6)
    x += k2; y += k0 + 5u;
#undef TF_R
    o0 = x; o1 = y;
}

__device__ __forceinline__ unsigned jax_random_bits32(unsigned k0, unsigned k1,
                                                      unsigned i) {
    unsigned a, b;
    threefry2x32(k0, k1, 0u, i, a, b);
    return a ^ b;
}

// ============================================================================
// XLA-exact elementwise ops (bit-identical to passing rounds)
// ============================================================================
__device__ __forceinline__ float bits_to_unit(unsigned b) {
    return __fsub_rn(__uint_as_float((b >> 9) | 0x3f800000u), 1.0f);
}

__device__ __forceinline__ float erfinv_xla(float x) {
    float w = -logf(__fmul_rn(__fsub_rn(1.0f, x), __fadd_rn(1.0f, x)));
    float p;
    if (w < 5.0f) {
        w = __fsub_rn(w, 2.5f);
        p = 2.81022636e-08f;
        p = __fadd_rn(3.43273939e-07f,  __fmul_rn(p, w));
        p = __fadd_rn(-3.5233877e-06f,  __fmul_rn(p, w));
        p = __fadd_rn(-4.39150654e-06f, __fmul_rn(p, w));
        p = __fadd_rn(0.00021858087f,   __fmul_rn(p, w));
        p = __fadd_rn(-0.00125372503f,  __fmul_rn(p, w));
        p = __fadd_rn(-0.00417768164f,  __fmul_rn(p, w));
        p = __fadd_rn(0.246640727f,     __fmul_rn(p, w));
        p = __fadd_rn(1.50140941f,      __fmul_rn(p, w));
    } else {
        w = __fsub_rn(sqrtf(w), 3.0f);
        p = -0.000200214257f;
        p = __fadd_rn(0.000100950558f,  __fmul_rn(p, w));
        p = __fadd_rn(0.00134934322f,   __fmul_rn(p, w));
        p = __fadd_rn(-0.00367342844f,  __fmul_rn(p, w));
        p = __fadd_rn(0.00573950773f,   __fmul_rn(p, w));
        p = __fadd_rn(-0.0076224613f,   __fmul_rn(p, w));
        p = __fadd_rn(0.00943887047f,   __fmul_rn(p, w));
        p = __fadd_rn(1.00167406f,      __fmul_rn(p, w));
        p = __fadd_rn(2.83297682f,      __fmul_rn(p, w));
    }
    return __fmul_rn(p, x);
}

__device__ __forceinline__ float jax_normal_from_bits(unsigned b) {
    float f = bits_to_unit(b);
    float u = __fadd_rn(__fmul_rn(f, 2.0f), -0.99999994f);
    u = fmaxf(u, -0.99999994f);
    return __fmul_rn(1.41421354f, erfinv_xla(u));
}

__device__ __forceinline__ float jax_gumbel_from_bits(unsigned b) {
    float f = bits_to_unit(b);
    float u = fmaxf(1.17549435e-38f, __fadd_rn(f, 1.17549435e-38f));
    return -logf(-logf(u));
}

__device__ __forceinline__ float xla_tanh(float x) {
    float ax = fabsf(x);
    float xc = fminf(fmaxf(x, -9.0f), 9.0f);
    float x2 = __fmul_rn(xc, xc);
    float p = -2.76076847742355e-16f;
    p = __fadd_rn(2.00018790482477e-13f, __fmul_rn(p, x2));
    p = __fadd_rn(-8.60467152213735e-11f, __fmul_rn(p, x2));
    p = __fadd_rn(5.12229709037114e-08f,  __fmul_rn(p, x2));
    p = __fadd_rn(1.48572235717979e-05f,  __fmul_rn(p, x2));
    p = __fadd_rn(6.37261928875436e-04f,  __fmul_rn(p, x2));
    p = __fadd_rn(4.89352455891786e-03f,  __fmul_rn(p, x2));
    float num = __fmul_rn(xc, p);
    float q = 1.19825839466702e-06f;
    q = __fadd_rn(1.18534705686654e-04f, __fmul_rn(q, x2));
    q = __fadd_rn(2.26843463243900e-03f, __fmul_rn(q, x2));
    q = __fadd_rn(4.89352518554385e-03f, __fmul_rn(q, x2));
    float r = __fdiv_rn(num, q);
    return (ax < 0.0004f) ? x : r;
}

// ============================================================================
// Packed fp32x2 helpers
// ============================================================================
__device__ __forceinline__ void fma2(unsigned long long &d,
                                     unsigned long long a,
                                     unsigned long long b) {
    asm("fma.rn.f32x2 %0, %1, %2, %0;" : "+l"(d) : "l"(a), "l"(b));
}
__device__ __forceinline__ void unpack2(unsigned long long v, float &lo, float &hi) {
    asm("mov.b64 {%0, %1}, %2;" : "=f"(lo), "=f"(hi) : "l"(v));
}
__device__ __forceinline__ unsigned long long dup2(float v) {
    unsigned long long r;
    asm("mov.b64 %0, {%1, %1};" : "=l"(r) : "f"(v));
    return r;
}

// ============================================================================
// prep: keys, scales, logdet, barrier reset
// ============================================================================
__global__ void prep_kernel(const float* __restrict__ sx,
                            const float* __restrict__ sy) {
    int i = threadIdx.x;   // 256
    if (i < H) g_sxstd[i] = sqrtf(sx[i]);
    if (i < BS) g_barrier[i] = 0u;
    unsigned sb0, sb1;
    threefry2x32(0u, 42u, 0u, 1u, sb0, sb1);
    unsigned o0, o1;
    threefry2x32(sb0, sb1, 0u, (unsigned)i, o0, o1);
    g_keybits[2*i]     = o0;
    g_keybits[2*i + 1] = o1;
    if (i == 0) {
        unsigned a, b;
        threefry2x32(0u, 42u, 0u, 0u, a, b);
        g_x0key[0] = a; g_x0key[1] = b;
    }
    if (i < 32) {
        float s = __fadd_rn(logf(sy[i]), logf(sy[i + 32]));
#pragma unroll
        for (int off = 16; off; off >>= 1)
            s = __fadd_rn(s, __shfl_down_sync(0xffffffffu, s, off));
        if (i == 0) {
            float t2 = __fmul_rn(32.0f, 1.8378770351409912f);
            g_logdet = __fadd_rn(__fmul_rn(0.5f, s), t2);
        }
    }
}

__global__ void x0_kernel() {
    int i = blockIdx.x * blockDim.x + threadIdx.x;
    unsigned bits = jax_random_bits32(g_x0key[0], g_x0key[1], (unsigned)i);
    g_x[i] = jax_normal_from_bits(bits);
}

// ============================================================================
// proj GEMM (runs once) — R9's 64x64 full-B core, unchanged
// ============================================================================
__device__ __forceinline__ void gemm_proj(const float* __restrict__ A,
                                          const float* __restrict__ B,
                                          float* smem,
                                          unsigned long long accp[4][2]) {
    float* Bsm = smem;                 // [256][68]
    float* As2 = smem + BS_FLOATS;     // [2][16][132]
    int tid = threadIdx.x;
#pragma unroll
    for (int it = 0; it < 16; it++) {
        int l = tid + 256 * it;
        int n = l & 63;
        int kq = (l >> 6) << 2;
        float4 v = *(const float4*)(B + (size_t)(blockIdx.y*64 + n)*256 + kq);
        Bsm[(kq+0)*68 + n] = v.x; Bsm[(kq+1)*68 + n] = v.y;
        Bsm[(kq+2)*68 + n] = v.z; Bsm[(kq+3)*68 + n] = v.w;
    }
    int arow = tid >> 2;
    int akq  = (tid & 3) << 2;
    const float* Ap = A + (size_t)(blockIdx.x*64 + arow)*256 + akq;
    int ty = tid >> 4, tx = tid & 15;
    {
        float4 av = *(const float4*)(Ap);
        float* d = As2;
        *(float2*)&d[(akq+0)*132 + arow*2] = make_float2(av.x, av.x);
        *(float2*)&d[(akq+1)*132 + arow*2] = make_float2(av.y, av.y);
        *(float2*)&d[(akq+2)*132 + arow*2] = make_float2(av.z, av.z);
        *(float2*)&d[(akq+3)*132 + arow*2] = make_float2(av.w, av.w);
    }
    __syncthreads();
    for (int c = 0; c < 16; c++) {
        float4 nv;
        if (c + 1 < 16) nv = *(const float4*)(Ap + (c+1)*16);
        const float* As = As2 + (c & 1) * (16*132);
        const float* Bc = Bsm + c * 16 * 68;
#pragma unroll
        for (int k = 0; k < 16; k++) {
            ulonglong2 bp  = *(const ulonglong2*)&Bc[k*68 + tx*4];
            ulonglong2 ad0 = *(const ulonglong2*)&As[k*132 + ty*8];
            ulonglong2 ad1 = *(const ulonglong2*)&As[k*132 + ty*8 + 4];
            fma2(accp[0][0], ad0.x, bp.x); fma2(accp[0][1], ad0.x, bp.y);
            fma2(accp[1][0], ad0.y, bp.x); fma2(accp[1][1], ad0.y, bp.y);
            fma2(accp[2][0], ad1.x, bp.x); fma2(accp[2][1], ad1.x, bp.y);
            fma2(accp[3][0], ad1.y, bp.x); fma2(accp[3][1], ad1.y, bp.y);
        }
        if (c + 1 < 16) {
            float* d = As2 + ((c+1) & 1) * (16*132);
            *(float2*)&d[(akq+0)*132 + arow*2] = make_float2(nv.x, nv.x);
            *(float2*)&d[(akq+1)*132 + arow*2] = make_float2(nv.y, nv.y);
            *(float2*)&d[(akq+2)*132 + arow*2] = make_float2(nv.z, nv.z);
            *(float2*)&d[(akq+3)*132 + arow*2] = make_float2(nv.w, nv.w);
        }
        __syncthreads();
    }
}

__global__ void __launch_bounds__(256, 2)
proj_kernel(const float* __restrict__ u, const float* __restrict__ W_ih,
            const float* __restrict__ b_ih) {
    extern __shared__ float smem[];
    unsigned long long accp[4][2] = {};
    gemm_proj(u, W_ih, smem, accp);
    int tx = threadIdx.x & 15, ty = threadIdx.x >> 4;
    int row0 = blockIdx.x * 64 + ty * 4;
    int col0 = blockIdx.y * 64 + tx * 4;
#pragma unroll
    for (int i = 0; i < 4; i++) {
        float v[4];
        unpack2(accp[i][0], v[0], v[1]);
        unpack2(accp[i][1], v[2], v[3]);
#pragma unroll
        for (int j = 0; j < 4; j++) {
            int c = col0 + j;
            g_proj[(size_t)(row0 + i) * H + c] = __fadd_rn(v[j], b_ih[c]);
        }
    }
}

// ============================================================================
// Persistent kernel: grid 128 (2 blocks per batch, 32 particles each),
// 512 threads, full 128-step loop. State in smem (dup f32x2 layout).
// ============================================================================
__global__ void __launch_bounds__(512, 1)
persist_kernel(const float* __restrict__ W_hh, const float* __restrict__ b_hh,
               const float* __restrict__ W1,  const float* __restrict__ b1,
               const float* __restrict__ W2,  const float* __restrict__ b2,
               const float* __restrict__ y,   const float* __restrict__ sy,
               float* __restrict__ out) {
    extern __shared__ float sm[];
    __shared__ float lp_s[NP];
    __shared__ float logw_s[NP];
    __shared__ float red_s[2];
    __shared__ int   I_s[32];

    int tid = threadIdx.x;
    int b    = blockIdx.x >> 1;
    int half = blockIdx.x & 1;
    int row0 = b*64 + half*32;

    // main-phase tile mapping: 8 rows x 2 cols per thread
    int cp = tid & 127;            // col pair -> cols cp*2, cp*2+1
    int rg = tid >> 7;             // 0..3 -> rows rg*8 .. +7
    // out-phase tile mapping: 2 rows x 2 cols
    int oty = tid >> 5;            // 0..15 -> rows oty*2
    int otx = tid & 31;            // cols otx*2
    int warp = tid >> 5, lane = tid & 31;

    float L = g_logdet;
    const float* yb = y;

    // ---- initial x load into dup layout ----
#pragma unroll
    for (int j = 0; j < 16; j++) {
        int lin = tid + 512*j;     // 0..8191
        int rl = lin & 31;
        int k  = lin >> 5;         // 0..255
        float v = g_x[(size_t)(row0 + rl)*256 + k];
        *(unsigned long long*)(sm + XD + k*68 + 2*rl) = dup2(v);
    }
    __syncthreads();

    for (int t = 0; t < T_STEPS; t++) {
        int par = t & 1;
        float* gh = g_h2 + (size_t)par * STATE_ELEMS;

        // ==================== Phase H: h = tanh(proj + x Whh^T + bhh) + noise
        {
            unsigned long long acc[8] = {};
            // loader mapping (W_hh [c][k] -> Bs[k][c])
            int lc0 = tid & 255,         lkq0 = (tid >> 8) * 4;
            int lc1 = (tid+512) & 255,   lkq1 = ((tid+512) >> 8) * 4;
            float4 pf0 = *(const float4*)(W_hh + (size_t)lc0*256 + lkq0);
            float4 pf1 = *(const float4*)(W_hh + (size_t)lc1*256 + lkq1);
            {
                float* Bd = sm + BSOFF;
                Bd[(lkq0+0)*264 + lc0] = pf0.x; Bd[(lkq0+1)*264 + lc0] = pf0.y;
                Bd[(lkq0+2)*264 + lc0] = pf0.z; Bd[(lkq0+3)*264 + lc0] = pf0.w;
                Bd[(lkq1+0)*264 + lc1] = pf1.x; Bd[(lkq1+1)*264 + lc1] = pf1.y;
                Bd[(lkq1+2)*264 + lc1] = pf1.z; Bd[(lkq1+3)*264 + lc1] = pf1.w;
            }
            __syncthreads();
            for (int ch = 0; ch < 16; ch++) {
                if (ch + 1 < 16) {
                    int k0 = (ch+1)*16;
                    pf0 = *(const float4*)(W_hh + (size_t)lc0*256 + k0 + lkq0);
                    pf1 = *(const float4*)(W_hh + (size_t)lc1*256 + k0 + lkq1);
                }
                const float* Bsb = sm + BSOFF + (ch & 1) * BSTRIDE;
#pragma unroll
                for (int kk = 0; kk < 16; kk++) {
                    const float* Ar = sm + XD + (ch*16 + kk)*68 + rg*16;
                    ulonglong2 a0 = *(const ulonglong2*)(Ar);
                    ulonglong2 a1 = *(const ulonglong2*)(Ar + 4);
                    ulonglong2 a2 = *(const ulonglong2*)(Ar + 8);
                    ulonglong2 a3 = *(const ulonglong2*)(Ar + 12);
                    unsigned long long bp =
                        *(const unsigned long long*)(Bsb + kk*264 + cp*2);
                    fma2(acc[0], a0.x, bp); fma2(acc[1], a0.y, bp);
                    fma2(acc[2], a1.x, bp); fma2(acc[3], a1.y, bp);
                    fma2(acc[4], a2.x, bp); fma2(acc[5], a2.y, bp);
                    fma2(acc[6], a3.x, bp); fma2(acc[7], a3.y, bp);
                }
                if (ch + 1 < 16) {
                    float* Bd = sm + BSOFF + ((ch+1) & 1) * BSTRIDE;
                    Bd[(lkq0+0)*264 + lc0] = pf0.x; Bd[(lkq0+1)*264 + lc0] = pf0.y;
                    Bd[(lkq0+2)*264 + lc0] = pf0.z; Bd[(lkq0+3)*264 + lc0] = pf0.w;
                    Bd[(lkq1+0)*264 + lc1] = pf1.x; Bd[(lkq1+1)*264 + lc1] = pf1.y;
                    Bd[(lkq1+2)*264 + lc1] = pf1.z; Bd[(lkq1+3)*264 + lc1] = pf1.w;
                }
                __syncthreads();
            }
            // epilogue
            unsigned k0 = g_keybits[4*t];
            unsigned k1 = g_keybits[4*t + 1];
            const float* projrow = g_proj + ((size_t)t * BS + b) * H;
            int c0 = cp*2;
#pragma unroll
            for (int jr = 0; jr < 8; jr++) {
                int rl = rg*8 + jr;
                int m  = row0 + rl;
                float v0, v1;
                unpack2(acc[jr], v0, v1);
                float pre0 = __fadd_rn(__fadd_rn(projrow[c0],   v0), b_hh[c0]);
                float pre1 = __fadd_rn(__fadd_rn(projrow[c0+1], v1), b_hh[c0+1]);
                unsigned bi0 = jax_random_bits32(k0, k1, (unsigned)(m*256 + c0));
                unsigned bi1 = jax_random_bits32(k0, k1, (unsigned)(m*256 + c0 + 1));
                float h0 = __fadd_rn(xla_tanh(pre0),
                                     __fmul_rn(jax_normal_from_bits(bi0), g_sxstd[c0]));
                float h1 = __fadd_rn(xla_tanh(pre1),
                                     __fmul_rn(jax_normal_from_bits(bi1), g_sxstd[c0+1]));
                *(float2*)&gh[(size_t)m*256 + c0] = make_float2(h0, h1);
                *(unsigned long long*)(sm + HD + (c0  )*68 + 2*rl) = dup2(h0);
                *(unsigned long long*)(sm + HD + (c0+1)*68 + 2*rl) = dup2(h1);
            }
        }
        __syncthreads();

        // ==================== Phase FFN: act = relu(h W1 + b1)
        {
            unsigned long long acc[8] = {};
            int lk0 = tid >> 6,        lnq0 = (tid & 63) * 4;
            int lk1 = (tid+512) >> 6,  lnq1 = (tid & 63) * 4;
            float4 pf0 = *(const float4*)(W1 + (size_t)lk0*256 + lnq0);
            float4 pf1 = *(const float4*)(W1 + (size_t)lk1*256 + lnq1);
            {
                float* Bd = sm + BSOFF;
                *(float4*)&Bd[lk0*264 + lnq0] = pf0;
                *(float4*)&Bd[lk1*264 + lnq1] = pf1;
            }
            __syncthreads();
            for (int ch = 0; ch < 16; ch++) {
                if (ch + 1 < 16) {
                    int k0 = (ch+1)*16;
                    pf0 = *(const float4*)(W1 + (size_t)(k0+lk0)*256 + lnq0);
                    pf1 = *(const float4*)(W1 + (size_t)(k0+lk1)*256 + lnq1);
                }
                const float* Bsb = sm + BSOFF + (ch & 1) * BSTRIDE;
#pragma unroll
                for (int kk = 0; kk < 16; kk++) {
                    const float* Ar = sm + HD + (ch*16 + kk)*68 + rg*16;
                    ulonglong2 a0 = *(const ulonglong2*)(Ar);
                    ulonglong2 a1 = *(const ulonglong2*)(Ar + 4);
                    ulonglong2 a2 = *(const ulonglong2*)(Ar + 8);
                    ulonglong2 a3 = *(const ulonglong2*)(Ar + 12);
                    unsigned long long bp =
                        *(const unsigned long long*)(Bsb + kk*264 + cp*2);
                    fma2(acc[0], a0.x, bp); fma2(acc[1], a0.y, bp);
                    fma2(acc[2], a1.x, bp); fma2(acc[3], a1.y, bp);
                    fma2(acc[4], a2.x, bp); fma2(acc[5], a2.y, bp);
                    fma2(acc[6], a3.x, bp); fma2(acc[7], a3.y, bp);
                }
                if (ch + 1 < 16) {
                    float* Bd = sm + BSOFF + ((ch+1) & 1) * BSTRIDE;
                    *(float4*)&Bd[lk0*264 + lnq0] = pf0;
                    *(float4*)&Bd[lk1*264 + lnq1] = pf1;
                }
                __syncthreads();
            }
            int c0 = cp*2;
#pragma unroll
            for (int jr = 0; jr < 8; jr++) {
                int rl = rg*8 + jr;
                float v0, v1;
                unpack2(acc[jr], v0, v1);
                float a0 = fmaxf(__fadd_rn(v0, b1[c0]),   0.0f);
                float a1 = fmaxf(__fadd_rn(v1, b1[c0+1]), 0.0f);
                *(unsigned long long*)(sm + XD + (c0  )*68 + 2*rl) = dup2(a0);
                *(unsigned long long*)(sm + XD + (c0+1)*68 + 2*rl) = dup2(a1);
            }
        }
        __syncthreads();

        // ==================== Phase OUT: yhat = act W2 + b2; lp
        {
            unsigned long long acc[2] = {};
            int lk = tid >> 4, lnq = (tid & 15) * 4;   // tid<256 loads
            float4 pf;
            if (tid < 256)
                pf = *(const float4*)(W2 + (size_t)lk*64 + lnq);
            if (tid < 256)
                *(float4*)&sm[BSOFF + lk*264 + lnq] = pf;
            __syncthreads();
            for (int ch = 0; ch < 16; ch++) {
                if (ch + 1 < 16 && tid < 256)
                    pf = *(const float4*)(W2 + (size_t)((ch+1)*16 + lk)*64 + lnq);
                const float* Bsb = sm + BSOFF + (ch & 1) * BSTRIDE;
#pragma unroll
                for (int kk = 0; kk < 16; kk++) {
                    const float* Ar = sm + XD + (ch*16 + kk)*68 + oty*4;
                    ulonglong2 a = *(const ulonglong2*)(Ar);
                    unsigned long long bp =
                        *(const unsigned long long*)(Bsb + kk*264 + otx*2);
                    fma2(acc[0], a.x, bp);
                    fma2(acc[1], a.y, bp);
                }
                if (ch + 1 < 16 && tid < 256)
                    *(float4*)&sm[BSOFF + (((ch+1)&1)*BSTRIDE) + lk*264 + lnq] = pf;
                __syncthreads();
            }
            const float* yrow = yb + ((size_t)t * BS + b) * OUTD;
            float* q_s = sm + QV;
            int c0 = otx*2;
#pragma unroll
            for (int ir = 0; ir < 2; ir++) {
                int n = oty*2 + ir;
                int m = row0 + n;
                float v0, v1;
                unpack2(acc[ir], v0, v1);
                float y0 = __fadd_rn(v0, b2[c0]);
                float y1 = __fadd_rn(v1, b2[c0+1]);
                *(float2*)&out[(((size_t)t * M_ROWS) + m) * OUTD + c0] =
                    make_float2(y0, y1);
                float d0 = __fsub_rn(y0, yrow[c0]);
                float d1 = __fsub_rn(y1, yrow[c0+1]);
                q_s[n*65 + c0]   = __fdiv_rn(__fmul_rn(d0, d0), sy[c0]);
                q_s[n*65 + c0+1] = __fdiv_rn(__fmul_rn(d1, d1), sy[c0+1]);
            }
            __syncthreads();
            // lp (XLA row-reduce order, per local n)
#pragma unroll
            for (int k2 = 0; k2 < 2; k2++) {
                int n = warp*2 + k2;
                float s = __fadd_rn(q_s[n*65 + lane], q_s[n*65 + lane + 32]);
#pragma unroll
                for (int off = 16; off; off >>= 1)
                    s = __fadd_rn(s, __shfl_down_sync(0xffffffffu, s, off));
                if (lane == 0)
                    g_lp[b*64 + half*32 + n] = __fsub_rn(-0.5f * s, L);
            }
        }
        __syncthreads();

        // ==================== pair barrier ====================
        if (tid == 0) {
            __threadfence();
            atomicAdd(&g_barrier[b], 1u);
            unsigned tgt = 2u * (unsigned)(t + 1);
            while (*((volatile unsigned*)&g_barrier[b]) < tgt)
                __nanosleep(64);
        }
        __syncthreads();
        __threadfence();

        // ==================== resample ====================
        if (tid < NP) lp_s[tid] = g_lp[b*64 + tid];
        __syncthreads();
        if (warp == 0) {
            float m1 = fmaxf(lp_s[lane], lp_s[lane + 32]);
#pragma unroll
            for (int off = 16; off; off >>= 1)
                m1 = fmaxf(m1, __shfl_down_sync(0xffffffffu, m1, off));
            m1 = __shfl_sync(0xffffffffu, m1, 0);
            float e1 = expf(__fsub_rn(lp_s[lane], m1));
            float e2 = expf(__fsub_rn(lp_s[lane + 32], m1));
            float s = __fadd_rn(e1, e2);
#pragma unroll
            for (int off = 16; off; off >>= 1)
                s = __fadd_rn(s, __shfl_down_sync(0xffffffffu, s, off));
            if (lane == 0) { red_s[0] = m1; red_s[1] = logf(s); }
        }
        __syncthreads();
        if (tid < NP)
            logw_s[tid] = __fsub_rn(__fsub_rn(lp_s[tid], red_s[0]), red_s[1]);
        __syncthreads();

        {
            float* v_s = sm + QV;   // [32][64]
            unsigned ck0 = g_keybits[4*t + 2];
            unsigned ck1 = g_keybits[4*t + 3];
#pragma unroll
            for (int j = 0; j < 4; j++) {
                int l = tid + 512*j;       // 0..2047
                int rl = l >> 6;
                int n  = l & 63;
                int r  = half*32 + rl;
                unsigned p = (unsigned)(4096*r + 64*b + n);
                unsigned bits = jax_random_bits32(ck0, ck1, p);
                v_s[rl*64 + n] = __fadd_rn(jax_gumbel_from_bits(bits), logw_s[n]);
            }
            __syncthreads();
            for (int rl = warp; rl < 32; rl += 16) {
                float v1 = v_s[rl*64 + lane];
                float v2 = v_s[rl*64 + 32 + lane];
                float val; int idx;
                if (v2 > v1) { val = v2; idx = lane + 32; }
                else         { val = v1; idx = lane; }
#pragma unroll
                for (int off = 16; off; off >>= 1) {
                    float ov = __shfl_down_sync(0xffffffffu, val, off);
                    int   oi = __shfl_down_sync(0xffffffffu, idx, off);
                    if (ov > val || (ov == val && oi < idx)) { val = ov; idx = oi; }
                }
                if (lane == 0) I_s[rl] = idx;
            }
            __syncthreads();
            // gather x = h[b, I, :] into dup layout
#pragma unroll
            for (int j = 0; j < 16; j++) {
                int lin = tid + 512*j;   // 0..8191
                int rl = lin & 31;
                int k  = lin >> 5;
                int src = I_s[rl];
                float v = gh[(size_t)(b*64 + src)*256 + k];
                *(unsigned long long*)(sm + XD + k*68 + 2*rl) = dup2(v);
            }
        }
        __syncthreads();
    }
}

// ============================================================================
// Launch
// ============================================================================
extern "C" void kernel_launch(void* const* d_in, const int* in_sizes, int n_in,
                              void* d_out, int out_size) {
    const float* u    = (const float*)d_in[0];
    const float* y    = (const float*)d_in[1];
    const float* W_ih = (const float*)d_in[2];
    const float* W_hh = (const float*)d_in[3];
    const float* b_ih = (const float*)d_in[4];
    const float* b_hh = (const float*)d_in[5];
    const float* W1   = (const float*)d_in[6];
    const float* b1   = (const float*)d_in[7];
    const float* W2   = (const float*)d_in[8];
    const float* b2   = (const float*)d_in[9];
    const float* sx   = (const float*)d_in[10];
    const float* sy   = (const float*)d_in[11];
    float* out = (float*)d_out;
    (void)in_sizes; (void)n_in; (void)out_size;

    cudaFuncSetAttribute(proj_kernel,
                         cudaFuncAttributeMaxDynamicSharedMemorySize, SMEM_BYTES);
    cudaFuncSetAttribute(persist_kernel,
                         cudaFuncAttributeMaxDynamicSharedMemorySize, PSMEM_BYTES);

    prep_kernel<<<1, 256>>>(sx, sy);
    x0_kernel<<<STATE_ELEMS / 256, 256>>>();
    proj_kernel<<<dim3(T_STEPS * BS / 64, H / 64), 256, SMEM_BYTES>>>(u, W_ih, b_ih);

    persist_kernel<<<2 * BS, 512, PSMEM_BYTES>>>(W_hh, b_hh, W1, b1, W2, b2,
                                                 y, sy, out);
}

// round 15
// speedup vs baseline: 1.0943x; 1.0943x over previous
#include <cuda_runtime.h>
#include <cuda_bf16.h>

// ============================================================================
// Problem constants
// ============================================================================
#define T_STEPS 128
#define BS      64
#define NP      64      // particles
#define H       256
#define OUTD    64
#define M_ROWS  (BS*NP)             // 4096 rows per state GEMM
#define STATE_ELEMS (BS*NP*H)       // 1048576

// proj (runs once) keeps the old 64x64 full-B core
#define BS_FLOATS   (256*68)        // 17408
#define AS2_FLOATS  (2*16*132)      // 4224
#define SMEM_BYTES  ((BS_FLOATS + AS2_FLOATS)*4)  // 86528

// h/ffn 32x64-tile core, K-chunk 32: Bs[2][32][68] + As[2][32][36]
#define HBS  (2*32*68)              // 4352
#define HAS  (2*32*36)              // 2304
#define SMEM_H_BYTES ((HBS + HAS)*4)   // 26624

// outres 64x64-tile core: Bs[2][16][68] + As[2][16][68]
#define OBS  (2*16*68)              // 2176
#define OAS  (2*16*68)              // 2176
#define SMEM_O_BYTES ((OBS + OAS)*4)   // 17408

// ============================================================================
// Device scratch
// ============================================================================
__device__ float g_x[STATE_ELEMS];        // particle state x  [BS*NP, H]
__device__ float g_h[STATE_ELEMS];        // h (post tanh+noise)
__device__ float g_act[STATE_ELEMS];      // FFN hidden activation
__device__ float g_proj[T_STEPS*BS*H];    // u @ W_ih^T + b_ih for all t
__device__ float g_sxstd[H];              // sqrt(sigma_x_diag)
__device__ float g_logdet;                // 0.5*sum(log sy) + 0.5*OUT*log2pi
__device__ unsigned g_keybits[512];       // split-foldlike keys
__device__ unsigned g_x0key[2];           // fold_in(key, 0)

// ============================================================================
// JAX Threefry-2x32 (partitionable mode)
// ============================================================================
__device__ __forceinline__ unsigned rotl32(unsigned v, int d) {
    return __funnelshift_l(v, v, d);
}

__device__ __forceinline__ void threefry2x32(unsigned k0, unsigned k1,
                                             unsigned x, unsigned y,
                                             unsigned &o0, unsigned &o1) {
    unsigned k2 = k0 ^ k1 ^ 0x1BD11BDAu;
    x += k0; y += k1;
#define TF_R(r) { x += y; y = rotl32(y, (r)); y ^= x; }
    TF_R(13) TF_R(15) TF_R(26) TF_R(6)
    x += k1; y += k2 + 1u;
    TF_R(17) TF_R(29) TF_R(16) TF_R(24)
    x += k2; y += k0 + 2u;
    TF_R(13) TF_R(15) TF_R(26) TF_R(6)
    x += k0; y += k1 + 3u;
    TF_R(17) TF_R(29) TF_R(16) TF_R(24)
    x += k1; y += k2 + 4u;
    TF_R(13) TF_R(15) TF_R(26) TF_R(6)
    x += k2; y += k0 + 5u;
#undef TF_R
    o0 = x; o1 = y;
}

__device__ __forceinline__ unsigned jax_random_bits32(unsigned k0, unsigned k1,
                                                      unsigned i) {
    unsigned a, b;
    threefry2x32(k0, k1, 0u, i, a, b);
    return a ^ b;
}

// ============================================================================
// XLA-exact elementwise ops (bit-identical)
// ============================================================================
__device__ __forceinline__ float bits_to_unit(unsigned b) {
    return __fsub_rn(__uint_as_float((b >> 9) | 0x3f800000u), 1.0f);
}

__device__ __forceinline__ float erfinv_xla(float x) {
    float w = -logf(__fmul_rn(__fsub_rn(1.0f, x), __fadd_rn(1.0f, x)));
    float p;
    if (w < 5.0f) {
        w = __fsub_rn(w, 2.5f);
        p = 2.81022636e-08f;
        p = __fadd_rn(3.43273939e-07f,  __fmul_rn(p, w));
        p = __fadd_rn(-3.5233877e-06f,  __fmul_rn(p, w));
        p = __fadd_rn(-4.39150654e-06f, __fmul_rn(p, w));
        p = __fadd_rn(0.00021858087f,   __fmul_rn(p, w));
        p = __fadd_rn(-0.00125372503f,  __fmul_rn(p, w));
        p = __fadd_rn(-0.00417768164f,  __fmul_rn(p, w));
        p = __fadd_rn(0.246640727f,     __fmul_rn(p, w));
        p = __fadd_rn(1.50140941f,      __fmul_rn(p, w));
    } else {
        w = __fsub_rn(sqrtf(w), 3.0f);
        p = -0.000200214257f;
        p = __fadd_rn(0.000100950558f,  __fmul_rn(p, w));
        p = __fadd_rn(0.00134934322f,   __fmul_rn(p, w));
        p = __fadd_rn(-0.00367342844f,  __fmul_rn(p, w));
        p = __fadd_rn(0.00573950773f,   __fmul_rn(p, w));
        p = __fadd_rn(-0.0076224613f,   __fmul_rn(p, w));
        p = __fadd_rn(0.00943887047f,   __fmul_rn(p, w));
        p = __fadd_rn(1.00167406f,      __fmul_rn(p, w));
        p = __fadd_rn(2.83297682f,      __fmul_rn(p, w));
    }
    return __fmul_rn(p, x);
}

__device__ __forceinline__ float jax_normal_from_bits(unsigned b) {
    float f = bits_to_unit(b);
    float u = __fadd_rn(__fmul_rn(f, 2.0f), -0.99999994f);
    u = fmaxf(u, -0.99999994f);
    return __fmul_rn(1.41421354f, erfinv_xla(u));
}

__device__ __forceinline__ float jax_gumbel_from_bits(unsigned b) {
    float f = bits_to_unit(b);
    float u = fmaxf(1.17549435e-38f, __fadd_rn(f, 1.17549435e-38f));
    return -logf(-logf(u));
}

__device__ __forceinline__ float xla_tanh(float x) {
    float ax = fabsf(x);
    float xc = fminf(fmaxf(x, -9.0f), 9.0f);
    float x2 = __fmul_rn(xc, xc);
    float p = -2.76076847742355e-16f;
    p = __fadd_rn(2.00018790482477e-13f, __fmul_rn(p, x2));
    p = __fadd_rn(-8.60467152213735e-11f, __fmul_rn(p, x2));
    p = __fadd_rn(5.12229709037114e-08f,  __fmul_rn(p, x2));
    p = __fadd_rn(1.48572235717979e-05f,  __fmul_rn(p, x2));
    p = __fadd_rn(6.37261928875436e-04f,  __fmul_rn(p, x2));
    p = __fadd_rn(4.89352455891786e-03f,  __fmul_rn(p, x2));
    float num = __fmul_rn(xc, p);
    float q = 1.19825839466702e-06f;
    q = __fadd_rn(1.18534705686654e-04f, __fmul_rn(q, x2));
    q = __fadd_rn(2.26843463243900e-03f, __fmul_rn(q, x2));
    q = __fadd_rn(4.89352518554385e-03f, __fmul_rn(q, x2));
    float r = __fdiv_rn(num, q);
    return (ax < 0.0004f) ? x : r;
}

// ============================================================================
// Packed fp32x2 helpers
// ============================================================================
__device__ __forceinline__ void fma2(unsigned long long &d,
                                     unsigned long long a,
                                     unsigned long long b) {
    asm("fma.rn.f32x2 %0, %1, %2, %0;" : "+l"(d) : "l"(a), "l"(b));
}
__device__ __forceinline__ void unpack2(unsigned long long v, float &lo, float &hi) {
    asm("mov.b64 {%0, %1}, %2;" : "=f"(lo), "=f"(hi) : "l"(v));
}
__device__ __forceinline__ unsigned long long dup2(float v) {
    unsigned long long r;
    asm("mov.b64 %0, {%1, %1};" : "=l"(r) : "f"(v));
    return r;
}

// ============================================================================
// Key / scale / logdet preparation
// ============================================================================
__global__ void prep_kernel(const float* __restrict__ sx,
                            const float* __restrict__ sy) {
    int i = threadIdx.x;   // 256 threads
    if (i < H) g_sxstd[i] = sqrtf(sx[i]);
    unsigned sb0, sb1;
    threefry2x32(0u, 42u, 0u, 1u, sb0, sb1);
    unsigned o0, o1;
    threefry2x32(sb0, sb1, 0u, (unsigned)i, o0, o1);
    g_keybits[2*i]     = o0;
    g_keybits[2*i + 1] = o1;
    if (i == 0) {
        unsigned a, b;
        threefry2x32(0u, 42u, 0u, 0u, a, b);
        g_x0key[0] = a; g_x0key[1] = b;
    }
    if (i < 32) {
        float s = __fadd_rn(logf(sy[i]), logf(sy[i + 32]));
#pragma unroll
        for (int off = 16; off; off >>= 1)
            s = __fadd_rn(s, __shfl_down_sync(0xffffffffu, s, off));
        if (i == 0) {
            float t2 = __fmul_rn(32.0f, 1.8378770351409912f);
            g_logdet = __fadd_rn(__fmul_rn(0.5f, s), t2);
        }
    }
}

__global__ void x0_kernel() {
    int i = blockIdx.x * blockDim.x + threadIdx.x;     // < 1048576
    unsigned bits = jax_random_bits32(g_x0key[0], g_x0key[1], (unsigned)i);
    g_x[i] = jax_normal_from_bits(bits);
}

// ============================================================================
// 32x64-tile GEMM core (h / ffn), 128 threads, 4 rows x 4 cols per thread.
// K-chunk = 32 (8 chunks, 9 syncs). A scalar in smem (broadcast LDS +
// register dup2). Ascending-k serial accumulation (bit-identical chains).
// BT = true : B is [N,256] row-major (C = A * B^T)
// BT = false: B is [256,N] row-major (C = A * B), leading dim ldb
// ============================================================================
template<bool BT>
__device__ __forceinline__ void gemm_32x64(const float* __restrict__ A,
                                           const float* __restrict__ B,
                                           int ldb, float* smem,
                                           unsigned long long acc[4][2]) {
    float* Bs = smem;              // [2][32][68]
    float* As = smem + HBS;        // [2][32][36]
    int tid = threadIdx.x;         // 0..127
    int tx = tid & 15, ty = tid >> 4;   // tx 0..15, ty 0..7

    int arow = tid >> 2;           // 0..31
    int akq  = (tid & 3) << 2;     // 0,4,8,12 (+16 for second load)
    const float* Ap = A + (size_t)(blockIdx.x*32 + arow)*256 + akq;

    int bn0 = blockIdx.y * 64;
    int bn_0 = 0, bn_1 = 0, bk_0 = 0, bnq = 0;
    const float *Bq00, *Bq01, *Bq10, *Bq11;
    if (BT) {
        bn_0 = tid >> 2;  bn_1 = bn_0 + 32;
        bk_0 = (tid & 3) << 2;
        const float* r0 = B + (size_t)(bn0 + bn_0)*256 + bk_0;
        const float* r1 = B + (size_t)(bn0 + bn_1)*256 + bk_0;
        Bq00 = r0; Bq01 = r0 + 16; Bq10 = r1; Bq11 = r1 + 16;
    } else {
        bk_0 = tid >> 4;
        bnq  = (tid & 15) << 2;
        Bq00 = B + (size_t)(bk_0     )*ldb + bn0 + bnq;
        Bq01 = B + (size_t)(bk_0 +  8)*ldb + bn0 + bnq;
        Bq10 = B + (size_t)(bk_0 + 16)*ldb + bn0 + bnq;
        Bq11 = B + (size_t)(bk_0 + 24)*ldb + bn0 + bnq;
    }

    // prologue: chunk 0 -> buf 0
    {
        float4 a0 = *(const float4*)(Ap);
        float4 a1 = *(const float4*)(Ap + 16);
        float4 b00 = *(const float4*)(Bq00);
        float4 b01 = *(const float4*)(Bq01);
        float4 b10 = *(const float4*)(Bq10);
        float4 b11 = *(const float4*)(Bq11);
        float* Asd = As;
        Asd[(akq+0)*36 + arow] = a0.x; Asd[(akq+1)*36 + arow] = a0.y;
        Asd[(akq+2)*36 + arow] = a0.z; Asd[(akq+3)*36 + arow] = a0.w;
        Asd[(akq+16)*36 + arow] = a1.x; Asd[(akq+17)*36 + arow] = a1.y;
        Asd[(akq+18)*36 + arow] = a1.z; Asd[(akq+19)*36 + arow] = a1.w;
        float* Bsd = Bs;
        if (BT) {
            Bsd[(bk_0+0)*68 + bn_0] = b00.x; Bsd[(bk_0+1)*68 + bn_0] = b00.y;
            Bsd[(bk_0+2)*68 + bn_0] = b00.z; Bsd[(bk_0+3)*68 + bn_0] = b00.w;
            Bsd[(bk_0+16)*68 + bn_0] = b01.x; Bsd[(bk_0+17)*68 + bn_0] = b01.y;
            Bsd[(bk_0+18)*68 + bn_0] = b01.z; Bsd[(bk_0+19)*68 + bn_0] = b01.w;
            Bsd[(bk_0+0)*68 + bn_1] = b10.x; Bsd[(bk_0+1)*68 + bn_1] = b10.y;
            Bsd[(bk_0+2)*68 + bn_1] = b10.z; Bsd[(bk_0+3)*68 + bn_1] = b10.w;
            Bsd[(bk_0+16)*68 + bn_1] = b11.x; Bsd[(bk_0+17)*68 + bn_1] = b11.y;
            Bsd[(bk_0+18)*68 + bn_1] = b11.z; Bsd[(bk_0+19)*68 + bn_1] = b11.w;
        } else {
            *(float4*)&Bsd[(bk_0     )*68 + bnq] = b00;
            *(float4*)&Bsd[(bk_0 +  8)*68 + bnq] = b01;
            *(float4*)&Bsd[(bk_0 + 16)*68 + bnq] = b10;
            *(float4*)&Bsd[(bk_0 + 24)*68 + bnq] = b11;
        }
    }
    __syncthreads();

    for (int c = 0; c < 8; c++) {
        float4 a0, a1, b00, b01, b10, b11;
        if (c + 1 < 8) {
            int off = (c+1)*32;
            a0 = *(const float4*)(Ap + off);
            a1 = *(const float4*)(Ap + off + 16);
            if (BT) {
                b00 = *(const float4*)(Bq00 + off);
                b01 = *(const float4*)(Bq01 + off);
                b10 = *(const float4*)(Bq10 + off);
                b11 = *(const float4*)(Bq11 + off);
            } else {
                size_t roff = (size_t)off * ldb;
                b00 = *(const float4*)(Bq00 + roff);
                b01 = *(const float4*)(Bq01 + roff);
                b10 = *(const float4*)(Bq10 + roff);
                b11 = *(const float4*)(Bq11 + roff);
            }
        }
        const float* Asb = As + (c & 1) * (32*36);
        const float* Bsb = Bs + (c & 1) * (32*68);
#pragma unroll
        for (int k = 0; k < 32; k++) {
            float4 a = *(const float4*)&Asb[k*36 + ty*4];
            ulonglong2 bp = *(const ulonglong2*)&Bsb[k*68 + tx*4];
            unsigned long long a0d = dup2(a.x), a1d = dup2(a.y);
            unsigned long long a2d = dup2(a.z), a3d = dup2(a.w);
            fma2(acc[0][0], a0d, bp.x); fma2(acc[0][1], a0d, bp.y);
            fma2(acc[1][0], a1d, bp.x); fma2(acc[1][1], a1d, bp.y);
            fma2(acc[2][0], a2d, bp.x); fma2(acc[2][1], a2d, bp.y);
            fma2(acc[3][0], a3d, bp.x); fma2(acc[3][1], a3d, bp.y);
        }
        if (c + 1 < 8) {
            float* Asd = As + ((c+1) & 1) * (32*36);
            Asd[(akq+0)*36 + arow] = a0.x; Asd[(akq+1)*36 + arow] = a0.y;
            Asd[(akq+2)*36 + arow] = a0.z; Asd[(akq+3)*36 + arow] = a0.w;
            Asd[(akq+16)*36 + arow] = a1.x; Asd[(akq+17)*36 + arow] = a1.y;
            Asd[(akq+18)*36 + arow] = a1.z; Asd[(akq+19)*36 + arow] = a1.w;
            float* Bsd = Bs + ((c+1) & 1) * (32*68);
            if (BT) {
                Bsd[(bk_0+0)*68 + bn_0] = b00.x; Bsd[(bk_0+1)*68 + bn_0] = b00.y;
                Bsd[(bk_0+2)*68 + bn_0] = b00.z; Bsd[(bk_0+3)*68 + bn_0] = b00.w;
                Bsd[(bk_0+16)*68 + bn_0] = b01.x; Bsd[(bk_0+17)*68 + bn_0] = b01.y;
                Bsd[(bk_0+18)*68 + bn_0] = b01.z; Bsd[(bk_0+19)*68 + bn_0] = b01.w;
                Bsd[(bk_0+0)*68 + bn_1] = b10.x; Bsd[(bk_0+1)*68 + bn_1] = b10.y;
                Bsd[(bk_0+2)*68 + bn_1] = b10.z; Bsd[(bk_0+3)*68 + bn_1] = b10.w;
                Bsd[(bk_0+16)*68 + bn_1] = b11.x; Bsd[(bk_0+17)*68 + bn_1] = b11.y;
                Bsd[(bk_0+18)*68 + bn_1] = b11.z; Bsd[(bk_0+19)*68 + bn_1] = b11.w;
            } else {
                *(float4*)&Bsd[(bk_0     )*68 + bnq] = b00;
                *(float4*)&Bsd[(bk_0 +  8)*68 + bnq] = b01;
                *(float4*)&Bsd[(bk_0 + 16)*68 + bnq] = b10;
                *(float4*)&Bsd[(bk_0 + 24)*68 + bnq] = b11;
            }
        }
        __syncthreads();
    }
}

// ============================================================================
// h = xla_tanh((proj + xW) + b_hh) + noise   (32x64 tile, fused RNG)
// ============================================================================
__global__ void __launch_bounds__(128, 4)
h_kernel(const float* __restrict__ W_hh, const float* __restrict__ b_hh, int t) {
    extern __shared__ float smem[];
    unsigned long long acc[4][2] = {};
    gemm_32x64<true>(g_x, W_hh, H, smem, acc);
    int tx = threadIdx.x & 15, ty = threadIdx.x >> 4;
    int row0 = blockIdx.x * 32 + ty * 4;
    int cb = blockIdx.y * 64;
    unsigned k0 = g_keybits[4*t];
    unsigned k1 = g_keybits[4*t + 1];
#pragma unroll
    for (int i = 0; i < 4; i++) {
        int m = row0 + i;
        int b = m >> 6;
        const float* projrow = g_proj + ((size_t)t * BS + b) * H;
#pragma unroll
        for (int p = 0; p < 2; p++) {
            float v[2];
            unpack2(acc[i][p], v[0], v[1]);
#pragma unroll
            for (int e = 0; e < 2; e++) {
                int c = cb + tx*4 + 2*p + e;
                size_t idx = (size_t)m * H + c;
                float pre = __fadd_rn(__fadd_rn(projrow[c], v[e]), b_hh[c]);
                unsigned bits = jax_random_bits32(k0, k1, (unsigned)idx);
                float nz = __fmul_rn(jax_normal_from_bits(bits), g_sxstd[c]);
                g_h[idx] = __fadd_rn(xla_tanh(pre), nz);
            }
        }
    }
}

// ============================================================================
// act = relu(h @ W1 + b1)   (32x64 tile)
// ============================================================================
__global__ void __launch_bounds__(128, 4)
ffn_kernel(const float* __restrict__ W1, const float* __restrict__ b1) {
    extern __shared__ float smem[];
    unsigned long long acc[4][2] = {};
    gemm_32x64<false>(g_h, W1, H, smem, acc);
    int tx = threadIdx.x & 15, ty = threadIdx.x >> 4;
    int row0 = blockIdx.x * 32 + ty * 4;
    int cb = blockIdx.y * 64;
#pragma unroll
    for (int i = 0; i < 4; i++) {
        int m = row0 + i;
#pragma unroll
        for (int p = 0; p < 2; p++) {
            float v[2];
            unpack2(acc[i][p], v[0], v[1]);
#pragma unroll
            for (int e = 0; e < 2; e++) {
                int c = cb + tx*4 + 2*p + e;
                g_act[(size_t)m * H + c] = fmaxf(__fadd_rn(v[e], b1[c]), 0.0f);
            }
        }
    }
}

// ============================================================================
// OLD 64x64 full-B GEMM core — proj only (runs once)
// ============================================================================
template<bool BT>
__device__ __forceinline__ void gemm_core(const float* __restrict__ A,
                                          const float* __restrict__ B,
                                          int ldb, float* smem,
                                          unsigned long long accp[4][2]) {
    float* Bsm = smem;                 // [256][68]
    float* As2 = smem + BS_FLOATS;     // [2][16][132]
    int tid = threadIdx.x;

    if (BT) {
#pragma unroll
        for (int it = 0; it < 16; it++) {
            int l = tid + 256 * it;
            int n = l & 63;
            int kq = (l >> 6) << 2;
            float4 v = *(const float4*)(B + (size_t)(blockIdx.y*64 + n)*256 + kq);
            Bsm[(kq+0)*68 + n] = v.x; Bsm[(kq+1)*68 + n] = v.y;
            Bsm[(kq+2)*68 + n] = v.z; Bsm[(kq+3)*68 + n] = v.w;
        }
    } else {
#pragma unroll
        for (int it = 0; it < 16; it++) {
            int l = tid + 256 * it;
            int k = l >> 4;
            int nq = (l & 15) << 2;
            float4 v = *(const float4*)(B + (size_t)k*ldb + blockIdx.y*64 + nq);
            *(float4*)&Bsm[k*68 + nq] = v;
        }
    }

    int arow = tid >> 2;
    int akq  = (tid & 3) << 2;
    const float* Ap = A + (size_t)(blockIdx.x*64 + arow)*256 + akq;
    int ty = tid >> 4, tx = tid & 15;

    {
        float4 av = *(const float4*)(Ap);
        float* d = As2;
        *(float2*)&d[(akq+0)*132 + arow*2] = make_float2(av.x, av.x);
        *(float2*)&d[(akq+1)*132 + arow*2] = make_float2(av.y, av.y);
        *(float2*)&d[(akq+2)*132 + arow*2] = make_float2(av.z, av.z);
        *(float2*)&d[(akq+3)*132 + arow*2] = make_float2(av.w, av.w);
    }
    __syncthreads();

    for (int c = 0; c < 16; c++) {
        float4 nv;
        if (c + 1 < 16) nv = *(const float4*)(Ap + (c+1)*16);
        const float* As = As2 + (c & 1) * (16*132);
        const float* Bc = Bsm + c * 16 * 68;
#pragma unroll
        for (int k = 0; k < 16; k++) {
            ulonglong2 bp  = *(const ulonglong2*)&Bc[k*68 + tx*4];
            ulonglong2 ad0 = *(const ulonglong2*)&As[k*132 + ty*8];
            ulonglong2 ad1 = *(const ulonglong2*)&As[k*132 + ty*8 + 4];
            fma2(accp[0][0], ad0.x, bp.x); fma2(accp[0][1], ad0.x, bp.y);
            fma2(accp[1][0], ad0.y, bp.x); fma2(accp[1][1], ad0.y, bp.y);
            fma2(accp[2][0], ad1.x, bp.x); fma2(accp[2][1], ad1.x, bp.y);
            fma2(accp[3][0], ad1.y, bp.x); fma2(accp[3][1], ad1.y, bp.y);
        }
        if (c + 1 < 16) {
            float* d = As2 + ((c+1) & 1) * (16*132);
            *(float2*)&d[(akq+0)*132 + arow*2] = make_float2(nv.x, nv.x);
            *(float2*)&d[(akq+1)*132 + arow*2] = make_float2(nv.y, nv.y);
            *(float2*)&d[(akq+2)*132 + arow*2] = make_float2(nv.z, nv.z);
            *(float2*)&d[(akq+3)*132 + arow*2] = make_float2(nv.w, nv.w);
        }
        __syncthreads();
    }
}

__device__ __forceinline__ void unpack_acc(unsigned long long accp[4][2],
                                           float acc[4][4]) {
#pragma unroll
    for (int i = 0; i < 4; i++) {
        unpack2(accp[i][0], acc[i][0], acc[i][1]);
        unpack2(accp[i][1], acc[i][2], acc[i][3]);
    }
}

// ============================================================================
// proj[t,b,:] = u[t,b,:] @ W_ih^T + b_ih  (runs once)
// ============================================================================
__global__ void __launch_bounds__(256, 2)
proj_kernel(const float* __restrict__ u, const float* __restrict__ W_ih,
            const float* __restrict__ b_ih) {
    extern __shared__ float smem[];
    unsigned long long accp[4][2] = {};
    gemm_core<true>(u, W_ih, H, smem, accp);
    float acc[4][4]; unpack_acc(accp, acc);
    int tx = threadIdx.x & 15, ty = threadIdx.x >> 4;
    int row0 = blockIdx.x * 64 + ty * 4;
    int col0 = blockIdx.y * 64 + tx * 4;
#pragma unroll
    for (int i = 0; i < 4; i++)
#pragma unroll
        for (int j = 0; j < 4; j++) {
            int c = col0 + j;
            g_proj[(size_t)(row0 + i) * H + c] = __fadd_rn(acc[i][j], b_ih[c]);
        }
}

// ============================================================================
// Fused outres (512 threads): y_hat -> out[t]; lp; log_softmax; gumbel
// argmax; resample gather. One block per batch; chunked 64x64 GEMM.
// ============================================================================
__global__ void __launch_bounds__(512, 1)
outres_kernel(const float* __restrict__ W2, const float* __restrict__ b2,
              const float* __restrict__ y, const float* __restrict__ sy,
              float* __restrict__ out, int t) {
    extern __shared__ float smem[];
    __shared__ float lp_s[NP];
    __shared__ float logw_s[NP];
    __shared__ int   I_s[NP];
    __shared__ float red_s[2];

    float* Bs = smem;              // [2][16][68]
    float* As = smem + OBS;        // [2][16][68]
    int tid = threadIdx.x;         // 0..511
    int tx = tid & 15, ty = tid >> 4;   // tx 0..15, ty 0..31
    int b = blockIdx.x;

    int arow = tid >> 2;                 // 0..63 (tid<256)
    int akq  = (tid & 3) << 2;
    const float* Ap = g_act + (size_t)(b*64 + arow)*256 + akq;
    int bk  = tid >> 4;                  // 0..15 (tid<256)
    int bnq = (tid & 15) << 2;
    const float* Bp = W2 + (size_t)bk*OUTD + bnq;

    unsigned long long acc[2][2] = {};

    if (tid < 256) {
        float4 av = *(const float4*)(Ap);
        float4 bv = *(const float4*)(Bp);
        As[(akq+0)*68 + arow] = av.x; As[(akq+1)*68 + arow] = av.y;
        As[(akq+2)*68 + arow] = av.z; As[(akq+3)*68 + arow] = av.w;
        *(float4*)&Bs[bk*68 + bnq] = bv;
    }
    __syncthreads();

    for (int c = 0; c < 16; c++) {
        float4 av, bv;
        if (c + 1 < 16 && tid < 256) {
            av = *(const float4*)(Ap + (c+1)*16);
            bv = *(const float4*)(Bp + (size_t)(c+1)*16*OUTD);
        }
        const float* Asb = As + (c & 1) * (16*68);
        const float* Bsb = Bs + (c & 1) * (16*68);
#pragma unroll
        for (int k = 0; k < 16; k++) {
            float2 a = *(const float2*)&Asb[k*68 + ty*2];
            ulonglong2 bp = *(const ulonglong2*)&Bsb[k*68 + tx*4];
            unsigned long long a0 = dup2(a.x), a1 = dup2(a.y);
            fma2(acc[0][0], a0, bp.x); fma2(acc[0][1], a0, bp.y);
            fma2(acc[1][0], a1, bp.x); fma2(acc[1][1], a1, bp.y);
        }
        if (c + 1 < 16 && tid < 256) {
            float* Asd = As + ((c+1) & 1) * (16*68);
            Asd[(akq+0)*68 + arow] = av.x; Asd[(akq+1)*68 + arow] = av.y;
            Asd[(akq+2)*68 + arow] = av.z; Asd[(akq+3)*68 + arow] = av.w;
            float* Bsd = Bs + ((c+1) & 1) * (16*68);
            *(float4*)&Bsd[bk*68 + bnq] = bv;
        }
        __syncthreads();
    }

    float* q_s = smem;                 // [64][65]
#pragma unroll
    for (int i = 0; i < 2; i++) {
        int n = ty * 2 + i;
        int m = b * 64 + n;
#pragma unroll
        for (int p = 0; p < 2; p++) {
            float v[2];
            unpack2(acc[i][p], v[0], v[1]);
#pragma unroll
            for (int e = 0; e < 2; e++) {
                int c = tx*4 + 2*p + e;
                float val = __fadd_rn(v[e], b2[c]);
                out[(((size_t)t * M_ROWS) + m) * OUTD + c] = val;
                float d = __fsub_rn(val, y[(((size_t)t * BS) + b) * OUTD + c]);
                q_s[n * 65 + c] = __fdiv_rn(__fmul_rn(d, d), sy[c]);
            }
        }
    }
    __syncthreads();

    int warp = tid >> 5, lane = tid & 31;
    float L = g_logdet;
#pragma unroll
    for (int k = 0; k < 4; k++) {
        int n = warp * 4 + k;
        float s = __fadd_rn(q_s[n * 65 + lane], q_s[n * 65 + lane + 32]);
#pragma unroll
        for (int off = 16; off; off >>= 1)
            s = __fadd_rn(s, __shfl_down_sync(0xffffffffu, s, off));
        if (lane == 0) lp_s[n] = __fsub_rn(-0.5f * s, L);
    }
    __syncthreads();

    if (warp == 0) {
        float m1 = fmaxf(lp_s[lane], lp_s[lane + 32]);
#pragma unroll
        for (int off = 16; off; off >>= 1)
            m1 = fmaxf(m1, __shfl_down_sync(0xffffffffu, m1, off));
        m1 = __shfl_sync(0xffffffffu, m1, 0);
        float e1 = expf(__fsub_rn(lp_s[lane], m1));
        float e2 = expf(__fsub_rn(lp_s[lane + 32], m1));
        float s = __fadd_rn(e1, e2);
#pragma unroll
        for (int off = 16; off; off >>= 1)
            s = __fadd_rn(s, __shfl_down_sync(0xffffffffu, s, off));
        if (lane == 0) { red_s[0] = m1; red_s[1] = logf(s); }
    }
    __syncthreads();
    if (tid < NP)
        logw_s[tid] = __fsub_rn(__fsub_rn(lp_s[tid], red_s[0]), red_s[1]);
    __syncthreads();

    float* v_s = smem;                 // [NP][NP]
    unsigned ck0 = g_keybits[4*t + 2];
    unsigned ck1 = g_keybits[4*t + 3];
    for (int l = tid; l < NP * NP; l += 512) {
        int r = l >> 6;
        int n = l & 63;
        unsigned p = (unsigned)(4096 * r + 64 * b + n);
        unsigned bits = jax_random_bits32(ck0, ck1, p);
        v_s[r * 64 + n] = __fadd_rn(jax_gumbel_from_bits(bits), logw_s[n]);
    }
    __syncthreads();

    for (int r = warp; r < NP; r += 16) {
        float v1 = v_s[r * 64 + lane];
        float v2 = v_s[r * 64 + 32 + lane];
        float val; int idx;
        if (v2 > v1) { val = v2; idx = lane + 32; }
        else         { val = v1; idx = lane; }
#pragma unroll
        for (int off = 16; off; off >>= 1) {
            float ov = __shfl_down_sync(0xffffffffu, val, off);
            int   oi = __shfl_down_sync(0xffffffffu, idx, off);
            if (ov > val || (ov == val && oi < idx)) { val = ov; idx = oi; }
        }
        if (lane == 0) I_s[r] = idx;
    }
    __syncthreads();

    const float4* hsrc = (const float4*)g_h;
    float4*       xdst = (float4*)g_x;
#pragma unroll
    for (int j = 0; j < 8; j++) {
        int lin = tid + 512 * j;       // 0..4095
        int r = lin >> 6;
        int c = lin & 63;
        int src = I_s[r];
        xdst[((size_t)(b * NP + r)) * 64 + c] =
            hsrc[((size_t)(b * NP + src)) * 64 + c];
    }
}

// ============================================================================
// Launch
// ============================================================================
extern "C" void kernel_launch(void* const* d_in, const int* in_sizes, int n_in,
                              void* d_out, int out_size) {
    const float* u    = (const float*)d_in[0];
    const float* y    = (const float*)d_in[1];
    const float* W_ih = (const float*)d_in[2];
    const float* W_hh = (const float*)d_in[3];
    const float* b_ih = (const float*)d_in[4];
    const float* b_hh = (const float*)d_in[5];
    const float* W1   = (const float*)d_in[6];
    const float* b1   = (const float*)d_in[7];
    const float* W2   = (const float*)d_in[8];
    const float* b2   = (const float*)d_in[9];
    const float* sx   = (const float*)d_in[10];
    const float* sy   = (const float*)d_in[11];
    float* out = (float*)d_out;
    (void)in_sizes; (void)n_in; (void)out_size;

    // only proj exceeds the 48KB default dynamic-smem limit
    cudaFuncSetAttribute(proj_kernel,
                         cudaFuncAttributeMaxDynamicSharedMemorySize, SMEM_BYTES);

    prep_kernel<<<1, 256>>>(sx, sy);
    x0_kernel<<<STATE_ELEMS / 256, 256>>>();
    proj_kernel<<<dim3(T_STEPS * BS / 64, H / 64), 256, SMEM_BYTES>>>(u, W_ih, b_ih);

    for (int t = 0; t < T_STEPS; t++) {
        h_kernel<<<dim3(M_ROWS / 32, H / 64), 128, SMEM_H_BYTES>>>(W_hh, b_hh, t);
        ffn_kernel<<<dim3(M_ROWS / 32, H / 64), 128, SMEM_H_BYTES>>>(W1, b1);
        outres_kernel<<<BS, 512, SMEM_O_BYTES>>>(W2, b2, y, sy, out, t);
    }
}